// round 5
// baseline (speedup 1.0000x reference)
#include <cuda_runtime.h>
#include <cuda_bf16.h>
#include <math.h>

// ---------------- problem constants ----------------
#define HID 768
#define NH 12
#define HD 64
#define FF 3072
#define NLAYER 12
#define CWIN 256
#define PDIM 128

#define B_DOC 2
#define S_DOC 2048
#define S_SUM 512
#define M_DOC (B_DOC * S_DOC)   // 4096
#define M_SUM (B_DOC * S_SUM)   // 1024

// ---------------- scratch (device globals; no allocation allowed) -------
__device__ __align__(256) float g_xdoc[M_DOC * HID];
__device__ __align__(256) float g_xsum[M_SUM * HID];
__device__ __align__(256) float g_q[M_DOC * HID];
__device__ __align__(256) float g_k[M_DOC * HID];
__device__ __align__(256) float g_v[M_DOC * HID];
__device__ __align__(256) float g_a[M_DOC * HID];
__device__ __align__(256) float g_t[M_DOC * HID];
__device__ __align__(256) float g_h[M_DOC * FF];
__device__ __align__(256) float g_emb[16 * HID];
__device__ __align__(256) float g_p1[16 * HID];
__device__ __align__(256) float g_p2[16 * PDIM];

// ---------------- helpers ----------------
__device__ __forceinline__ float block_sum_256(float v) {
    __shared__ float sh[8];
    #pragma unroll
    for (int o = 16; o > 0; o >>= 1) v += __shfl_xor_sync(0xffffffffu, v, o);
    int w = threadIdx.x >> 5;
    if ((threadIdx.x & 31) == 0) sh[w] = v;
    __syncthreads();
    if (threadIdx.x < 8) {
        float r = sh[threadIdx.x];
        #pragma unroll
        for (int o = 4; o > 0; o >>= 1) r += __shfl_xor_sync(0x000000ffu, r, o);
        if (threadIdx.x == 0) sh[0] = r;
    }
    __syncthreads();
    float out = sh[0];
    __syncthreads();   // protect shared buffer for next call
    return out;
}

// ---------------- embedding + layernorm (one block per token, 256 thr) ---
__global__ void embed_ln_kernel(const int* __restrict__ ids,
                                const float* __restrict__ wemb,
                                const float* __restrict__ pemb,
                                const float* __restrict__ tt,
                                const float* __restrict__ gam,
                                const float* __restrict__ bet,
                                float* __restrict__ out, int S) {
    int tok = blockIdx.x;
    int s = tok % S;
    int id = ids[tok];
    float vv[3];
    float sum = 0.f;
    #pragma unroll
    for (int kk = 0; kk < 3; kk++) {
        int h = threadIdx.x + kk * 256;
        vv[kk] = wemb[(size_t)id * HID + h] + pemb[(size_t)(s + 2) * HID + h] + tt[h];
        sum += vv[kk];
    }
    sum = block_sum_256(sum);
    float mu = sum * (1.f / HID);
    float q = 0.f;
    #pragma unroll
    for (int kk = 0; kk < 3; kk++) { float d = vv[kk] - mu; q += d * d; }
    q = block_sum_256(q);
    float r = rsqrtf(q * (1.f / HID) + 1e-5f);
    #pragma unroll
    for (int kk = 0; kk < 3; kk++) {
        int h = threadIdx.x + kk * 256;
        out[(size_t)tok * HID + h] = (vv[kk] - mu) * r * gam[h] + bet[h];
    }
}

// ---------------- residual add + layernorm (one block per row) ----------
__global__ void add_ln_kernel(const float* __restrict__ xin,
                              const float* __restrict__ dres,
                              const float* __restrict__ gam,
                              const float* __restrict__ bet,
                              float* __restrict__ xout) {
    size_t base = (size_t)blockIdx.x * HID;
    float vv[3];
    float sum = 0.f;
    #pragma unroll
    for (int kk = 0; kk < 3; kk++) {
        int h = threadIdx.x + kk * 256;
        vv[kk] = xin[base + h] + dres[base + h];
        sum += vv[kk];
    }
    sum = block_sum_256(sum);
    float mu = sum * (1.f / HID);
    float q = 0.f;
    #pragma unroll
    for (int kk = 0; kk < 3; kk++) { float d = vv[kk] - mu; q += d * d; }
    q = block_sum_256(q);
    float r = rsqrtf(q * (1.f / HID) + 1e-5f);
    #pragma unroll
    for (int kk = 0; kk < 3; kk++) {
        int h = threadIdx.x + kk * 256;
        xout[base + h] = (vv[kk] - mu) * r * gam[h] + bet[h];
    }
}

// ---------------- SGEMM: C[M,N] = A[M,K] @ B[K,N] + bias, epilogue ------
// EPI: 0 = none, 1 = exact gelu, 2 = relu.  BM=BN=128, BK=16, 256 threads,
// 8x8 microtile. N and K must be multiples of 16/128 resp. (they are); M guarded.
template <int EPI>
__global__ __launch_bounds__(256)
void sgemm_kernel(const float* __restrict__ A, const float* __restrict__ B,
                  const float* __restrict__ bias, float* __restrict__ C,
                  int M, int N, int K) {
    const int BM = 128, BN = 128, BK = 16;
    __shared__ float As[BK][BM];
    __shared__ float Bs[BK][BN];
    int tid = threadIdx.x;
    int row0 = blockIdx.y * BM, col0 = blockIdx.x * BN;
    int arow = tid >> 1;                 // 0..127
    int acol = (tid & 1) * 8;            // 0 or 8
    int brow = tid >> 5;                 // 0..7
    int bcol = (tid & 31) * 4;           // 0..124
    int tx = tid & 15, ty = tid >> 4;
    float acc[8][8];
    #pragma unroll
    for (int i = 0; i < 8; i++)
        #pragma unroll
        for (int j = 0; j < 8; j++) acc[i][j] = 0.f;

    for (int k0 = 0; k0 < K; k0 += BK) {
        // load A tile (transposed into smem), zero-fill rows >= M
        #pragma unroll
        for (int it = 0; it < 2; it++) {
            float4 v = make_float4(0.f, 0.f, 0.f, 0.f);
            int r = row0 + arow;
            if (r < M) v = *(const float4*)&A[(size_t)r * K + k0 + acol + it * 4];
            int kc = acol + it * 4;
            As[kc + 0][arow] = v.x; As[kc + 1][arow] = v.y;
            As[kc + 2][arow] = v.z; As[kc + 3][arow] = v.w;
        }
        // load B tile
        #pragma unroll
        for (int it = 0; it < 2; it++) {
            int r = brow + it * 8;
            float4 v = *(const float4*)&B[(size_t)(k0 + r) * N + col0 + bcol];
            *(float4*)&Bs[r][bcol] = v;
        }
        __syncthreads();
        #pragma unroll
        for (int k = 0; k < BK; k++) {
            float a[8], b[8];
            float4 a0 = *(const float4*)&As[k][ty * 8];
            float4 a1 = *(const float4*)&As[k][ty * 8 + 4];
            a[0] = a0.x; a[1] = a0.y; a[2] = a0.z; a[3] = a0.w;
            a[4] = a1.x; a[5] = a1.y; a[6] = a1.z; a[7] = a1.w;
            float4 b0 = *(const float4*)&Bs[k][tx * 8];
            float4 b1 = *(const float4*)&Bs[k][tx * 8 + 4];
            b[0] = b0.x; b[1] = b0.y; b[2] = b0.z; b[3] = b0.w;
            b[4] = b1.x; b[5] = b1.y; b[6] = b1.z; b[7] = b1.w;
            #pragma unroll
            for (int i = 0; i < 8; i++)
                #pragma unroll
                for (int j = 0; j < 8; j++) acc[i][j] += a[i] * b[j];
        }
        __syncthreads();
    }

    #pragma unroll
    for (int i = 0; i < 8; i++) {
        int r = row0 + ty * 8 + i;
        if (r >= M) continue;
        #pragma unroll
        for (int j = 0; j < 8; j++) {
            int c = col0 + tx * 8 + j;
            float v = acc[i][j] + bias[c];
            if (EPI == 1) v = 0.5f * v * (1.f + erff(v * 0.70710678118654752440f));
            if (EPI == 2) v = fmaxf(v, 0.f);
            C[(size_t)r * N + c] = v;
        }
    }
}

// ---------------- sliding-window attention --------------------------------
// grid: (nc*4, NH, B); block 128 threads. Each block: 64 queries of one chunk,
// online-softmax over the 3c=768-key window in 32-key tiles.
// Layout of q/k/v/out: [b, s, h*64+d] row-major (stride HID).
__global__ __launch_bounds__(128)
void slide_attn_kernel(const float* __restrict__ q, const float* __restrict__ k,
                       const float* __restrict__ v, const int* __restrict__ amask,
                       float* __restrict__ out, int S) {
    __shared__ float Qs[64][68];
    __shared__ float Ks[32][68];
    __shared__ float Vs[32][68];
    __shared__ int kval[32];

    int n = blockIdx.x >> 2, qt = blockIdx.x & 3;
    int h = blockIdx.y, b = blockIdx.z;
    int tid = threadIdx.x;
    int q0 = n * CWIN + qt * 64;          // first global query row of this block

    // stage Q tile (pre-scaled by 1/sqrt(64))
    #pragma unroll
    for (int it = 0; it < 8; it++) {
        int lin = tid + it * 128;          // 0..1023
        int r = lin >> 4, d4 = (lin & 15) * 4;
        float4 qv = *(const float4*)&q[((size_t)(b * S + q0 + r)) * HID + h * HD + d4];
        qv.x *= 0.125f; qv.y *= 0.125f; qv.z *= 0.125f; qv.w *= 0.125f;
        *(float4*)&Qs[r][d4] = qv;
    }

    int row = tid >> 1, half = tid & 1;
    int iq = qt * 64 + row;                // query index within chunk (0..255)
    int kbase = n * CWIN - CWIN;           // global key index at t=0
    float m = -1e30f, l = 0.f;
    float acc[64];
    #pragma unroll
    for (int d = 0; d < 64; d++) acc[d] = 0.f;

    for (int j0 = 0; j0 < 3 * CWIN; j0 += 32) {
        __syncthreads();
        // stage K,V tile (32 keys)
        #pragma unroll
        for (int it = 0; it < 4; it++) {
            int lin = tid + it * 128;      // 0..511
            int jj = lin >> 4, d4 = (lin & 15) * 4;
            int g = kbase + j0 + jj;
            bool ok = (g >= 0) && (g < S) && (amask[b * S + g] != 0);
            float4 kv = make_float4(0.f, 0.f, 0.f, 0.f);
            float4 vv = make_float4(0.f, 0.f, 0.f, 0.f);
            if (ok) {
                size_t off = ((size_t)(b * S + g)) * HID + h * HD + d4;
                kv = *(const float4*)&k[off];
                vv = *(const float4*)&v[off];
            }
            *(float4*)&Ks[jj][d4] = kv;
            *(float4*)&Vs[jj][d4] = vv;
            if (d4 == 0) kval[jj] = ok ? 1 : 0;
        }
        __syncthreads();

        // scores: this thread covers 16 keys = [half*16, half*16+16)
        float s[16];
        #pragma unroll
        for (int u = 0; u < 16; u++) s[u] = 0.f;
        #pragma unroll
        for (int d4 = 0; d4 < 64; d4 += 4) {
            float4 qv = *(const float4*)&Qs[row][d4];
            #pragma unroll
            for (int u = 0; u < 16; u++) {
                float4 kv = *(const float4*)&Ks[half * 16 + u][d4];
                s[u] += qv.x * kv.x + qv.y * kv.y + qv.z * kv.z + qv.w * kv.w;
            }
        }
        // band + padding mask (matches reference's -1e9 fill exactly)
        float tmax = -1e30f;
        #pragma unroll
        for (int u = 0; u < 16; u++) {
            int t = j0 + half * 16 + u;
            bool valid = (t >= iq) && (t <= iq + 2 * CWIN) && (kval[half * 16 + u] != 0);
            s[u] = valid ? s[u] : -1e9f;
            tmax = fmaxf(tmax, s[u]);
        }
        tmax = fmaxf(tmax, __shfl_xor_sync(0xffffffffu, tmax, 1));
        float mnew = fmaxf(m, tmax);
        float corr = __expf(m - mnew);
        l *= corr;
        #pragma unroll
        for (int d = 0; d < 64; d++) acc[d] *= corr;
        #pragma unroll
        for (int u = 0; u < 16; u++) {
            float p = __expf(s[u] - mnew);
            l += p;
            #pragma unroll
            for (int d4 = 0; d4 < 64; d4 += 4) {
                float4 vv = *(const float4*)&Vs[half * 16 + u][d4];
                acc[d4 + 0] += p * vv.x; acc[d4 + 1] += p * vv.y;
                acc[d4 + 2] += p * vv.z; acc[d4 + 3] += p * vv.w;
            }
        }
        m = mnew;
    }

    // merge the two key-halves of this row
    l += __shfl_xor_sync(0xffffffffu, l, 1);
    #pragma unroll
    for (int d = 0; d < 64; d++) acc[d] += __shfl_xor_sync(0xffffffffu, acc[d], 1);
    float inv = 1.f / l;
    size_t obase = ((size_t)(b * S + q0 + row)) * HID + h * HD + half * 32;
    #pragma unroll
    for (int d = 0; d < 32; d++) out[obase + d] = acc[half * 32 + d] * inv;
}

// ---------------- span pooling ------------------------------------------
__global__ void span_pool_kernel(const float* __restrict__ masks,
                                 const float* __restrict__ seq,
                                 const int* __restrict__ sidx,
                                 float* __restrict__ emb, int S) {
    int t = blockIdx.x;
    int b = sidx[t];
    __shared__ float mch[256];
    float lenp = 0.f;
    for (int s = threadIdx.x; s < S; s += 256) lenp += masks[t * S + s];
    float len = block_sum_256(lenp);
    len = fmaxf(len, 1e-9f);
    float e[3] = {0.f, 0.f, 0.f};
    for (int s0 = 0; s0 < S; s0 += 256) {
        __syncthreads();
        mch[threadIdx.x] = masks[t * S + s0 + threadIdx.x];
        __syncthreads();
        for (int ss = 0; ss < 256; ss++) {
            float mv = mch[ss];
            size_t base = ((size_t)(b * S + s0 + ss)) * HID;
            #pragma unroll
            for (int kk = 0; kk < 3; kk++)
                e[kk] += mv * seq[base + threadIdx.x + kk * 256];
        }
    }
    float inv = 1.f / len;
    #pragma unroll
    for (int kk = 0; kk < 3; kk++)
        emb[t * HID + threadIdx.x + kk * 256] = e[kk] * inv;
}

// ---------------- row-wise L2 normalize (16 rows x 128) ------------------
__global__ void l2norm_kernel(const float* __restrict__ p, float* __restrict__ out) {
    int t = blockIdx.x;
    float v = p[t * PDIM + threadIdx.x];
    float sq = v * v;
    __shared__ float sh[4];
    #pragma unroll
    for (int o = 16; o > 0; o >>= 1) sq += __shfl_xor_sync(0xffffffffu, sq, o);
    int w = threadIdx.x >> 5;
    if ((threadIdx.x & 31) == 0) sh[w] = sq;
    __syncthreads();
    float nrm = sqrtf(sh[0] + sh[1] + sh[2] + sh[3]);
    out[t * PDIM + threadIdx.x] = v / fmaxf(nrm, 1e-12f);
}

// ---------------- host orchestration ------------------------------------
struct Weights {
    const float *wemb, *pemb, *tt, *lng, *lnb;
    const float *Wq, *bq, *Wk, *bk, *Wv, *bv, *Wo, *bo;
    const float *ln1g, *ln1b, *W1, *b1, *W2, *b2, *ln2g, *ln2b;
};

static void run_encoder(const int* ids, const int* am, int B, int S, float* x,
                        float* qb, float* kb, float* vb, float* ab, float* tb,
                        float* hb, const Weights& W) {
    int M = B * S;
    embed_ln_kernel<<<M, 256>>>(ids, W.wemb, W.pemb, W.tt, W.lng, W.lnb, x, S);
    int nc = S / CWIN;
    dim3 g768(HID / 128, M / 128);
    dim3 gff(FF / 128, M / 128);
    for (int l = 0; l < NLAYER; l++) {
        const float* wq = W.Wq + (size_t)l * HID * HID;
        const float* wk = W.Wk + (size_t)l * HID * HID;
        const float* wv = W.Wv + (size_t)l * HID * HID;
        const float* wo = W.Wo + (size_t)l * HID * HID;
        const float* w1 = W.W1 + (size_t)l * HID * FF;
        const float* w2 = W.W2 + (size_t)l * FF * HID;
        sgemm_kernel<0><<<g768, 256>>>(x, wq, W.bq + l * HID, qb, M, HID, HID);
        sgemm_kernel<0><<<g768, 256>>>(x, wk, W.bk + l * HID, kb, M, HID, HID);
        sgemm_kernel<0><<<g768, 256>>>(x, wv, W.bv + l * HID, vb, M, HID, HID);
        slide_attn_kernel<<<dim3(nc * 4, NH, B), 128>>>(qb, kb, vb, am, ab, S);
        sgemm_kernel<0><<<g768, 256>>>(ab, wo, W.bo + l * HID, tb, M, HID, HID);
        add_ln_kernel<<<M, 256>>>(x, tb, W.ln1g + l * HID, W.ln1b + l * HID, x);
        sgemm_kernel<1><<<gff, 256>>>(x, w1, W.b1 + l * FF, hb, M, FF, HID);
        sgemm_kernel<0><<<g768, 256>>>(hb, w2, W.b2 + l * HID, tb, M, HID, FF);
        add_ln_kernel<<<M, 256>>>(x, tb, W.ln2g + l * HID, W.ln2b + l * HID, x);
    }
}

extern "C" void kernel_launch(void* const* d_in, const int* in_sizes, int n_in,
                              void* d_out, int out_size) {
    const int*   doc_ids   = (const int*)d_in[0];
    const int*   doc_am    = (const int*)d_in[1];
    const int*   sum_ids   = (const int*)d_in[2];
    const int*   sum_am    = (const int*)d_in[3];
    const float* og_masks  = (const float*)d_in[4];
    const float* llm_masks = (const float*)d_in[5];
    const int*   sidx      = (const int*)d_in[6];

    Weights W;
    W.wemb = (const float*)d_in[7];
    W.pemb = (const float*)d_in[8];
    W.tt   = (const float*)d_in[9];
    W.lng  = (const float*)d_in[10];
    W.lnb  = (const float*)d_in[11];
    W.Wq = (const float*)d_in[12]; W.bq = (const float*)d_in[13];
    W.Wk = (const float*)d_in[14]; W.bk = (const float*)d_in[15];
    W.Wv = (const float*)d_in[16]; W.bv = (const float*)d_in[17];
    W.Wo = (const float*)d_in[18]; W.bo = (const float*)d_in[19];
    W.ln1g = (const float*)d_in[20]; W.ln1b = (const float*)d_in[21];
    W.W1 = (const float*)d_in[22]; W.b1 = (const float*)d_in[23];
    W.W2 = (const float*)d_in[24]; W.b2 = (const float*)d_in[25];
    W.ln2g = (const float*)d_in[26]; W.ln2b = (const float*)d_in[27];
    const float* pW1 = (const float*)d_in[28];
    const float* pb1 = (const float*)d_in[29];
    const float* pW2 = (const float*)d_in[30];
    const float* pb2 = (const float*)d_in[31];
    float* out = (float*)d_out;

    float *xdoc, *xsum, *qb, *kb, *vb, *ab, *tb, *hb, *emb, *p1, *p2;
    cudaGetSymbolAddress((void**)&xdoc, g_xdoc);
    cudaGetSymbolAddress((void**)&xsum, g_xsum);
    cudaGetSymbolAddress((void**)&qb, g_q);
    cudaGetSymbolAddress((void**)&kb, g_k);
    cudaGetSymbolAddress((void**)&vb, g_v);
    cudaGetSymbolAddress((void**)&ab, g_a);
    cudaGetSymbolAddress((void**)&tb, g_t);
    cudaGetSymbolAddress((void**)&hb, g_h);
    cudaGetSymbolAddress((void**)&emb, g_emb);
    cudaGetSymbolAddress((void**)&p1, g_p1);
    cudaGetSymbolAddress((void**)&p2, g_p2);

    // two encoder passes
    run_encoder(doc_ids, doc_am, B_DOC, S_DOC, xdoc, qb, kb, vb, ab, tb, hb, W);
    run_encoder(sum_ids, sum_am, B_DOC, S_SUM, xsum, qb, kb, vb, ab, tb, hb, W);

    // human spans (doc)
    span_pool_kernel<<<16, 256>>>(og_masks, xdoc, sidx, emb, S_DOC);
    sgemm_kernel<2><<<dim3(HID / 128, 1), 256>>>(emb, pW1, pb1, p1, 16, HID, HID);
    sgemm_kernel<0><<<dim3(PDIM / 128, 1), 256>>>(p1, pW2, pb2, p2, 16, PDIM, HID);
    l2norm_kernel<<<16, PDIM>>>(p2, out);

    // llm spans (summary)
    span_pool_kernel<<<16, 256>>>(llm_masks, xsum, sidx, emb, S_SUM);
    sgemm_kernel<2><<<dim3(HID / 128, 1), 256>>>(emb, pW1, pb1, p1, 16, HID, HID);
    sgemm_kernel<0><<<dim3(PDIM / 128, 1), 256>>>(p1, pW2, pb2, p2, 16, PDIM, HID);
    l2norm_kernel<<<16, PDIM>>>(p2, out + 16 * PDIM);
}

// round 9
// speedup vs baseline: 2.4716x; 2.4716x over previous
#include <cuda_runtime.h>
#include <cuda_bf16.h>
#include <math.h>

// ---------------- problem constants ----------------
#define HID 768
#define NH 12
#define HD 64
#define FF 3072
#define NLAYER 12
#define CWIN 256
#define PDIM 128

#define B_DOC 2
#define S_DOC 2048
#define S_SUM 512
#define M_DOC (B_DOC * S_DOC)   // 4096
#define M_SUM (B_DOC * S_SUM)   // 1024

// ---------------- scratch (device globals; no allocation allowed) -------
__device__ __align__(256) float g_xdoc[M_DOC * HID];
__device__ __align__(256) float g_xsum[M_SUM * HID];
__device__ __align__(256) float g_q[M_DOC * HID];
__device__ __align__(256) float g_k[M_DOC * HID];
__device__ __align__(256) float g_v[M_DOC * HID];
__device__ __align__(256) float g_a[M_DOC * HID];
__device__ __align__(256) float g_t[M_DOC * HID];
__device__ __align__(256) float g_h[M_DOC * FF];
__device__ __align__(256) float g_emb[16 * HID];
__device__ __align__(256) float g_p1[16 * HID];
__device__ __align__(256) float g_p2[16 * PDIM];

// ---------------- helpers ----------------
__device__ __forceinline__ float block_sum_256(float v) {
    __shared__ float sh[8];
    #pragma unroll
    for (int o = 16; o > 0; o >>= 1) v += __shfl_xor_sync(0xffffffffu, v, o);
    int w = threadIdx.x >> 5;
    if ((threadIdx.x & 31) == 0) sh[w] = v;
    __syncthreads();
    if (threadIdx.x < 8) {
        float r = sh[threadIdx.x];
        #pragma unroll
        for (int o = 4; o > 0; o >>= 1) r += __shfl_xor_sync(0x000000ffu, r, o);
        if (threadIdx.x == 0) sh[0] = r;
    }
    __syncthreads();
    float out = sh[0];
    __syncthreads();
    return out;
}

__device__ __forceinline__ unsigned smem_u32(const void* p) {
    return (unsigned)__cvta_generic_to_shared(p);
}

__device__ __forceinline__ void cp16(unsigned s, const void* g, bool pred) {
    asm volatile("cp.async.cg.shared.global [%0], [%1], 16, %2;\n"
                 :: "r"(s), "l"(g), "r"(pred ? 16 : 0));
}

__device__ __forceinline__ unsigned f2tf(float x) {
    unsigned r;
    asm("cvt.rna.tf32.f32 %0, %1;" : "=r"(r) : "f"(x));
    return r;
}

__device__ __forceinline__ void mma8(float* c, const unsigned* a, const unsigned* b) {
    asm volatile(
        "mma.sync.aligned.m16n8k8.row.col.f32.tf32.tf32.f32 "
        "{%0,%1,%2,%3}, {%4,%5,%6,%7}, {%8,%9}, {%0,%1,%2,%3};"
        : "+f"(c[0]), "+f"(c[1]), "+f"(c[2]), "+f"(c[3])
        : "r"(a[0]), "r"(a[1]), "r"(a[2]), "r"(a[3]), "r"(b[0]), "r"(b[1]));
}

// ---------------- embedding + layernorm ----------------------------------
__global__ void embed_ln_kernel(const int* __restrict__ ids,
                                const float* __restrict__ wemb,
                                const float* __restrict__ pemb,
                                const float* __restrict__ tt,
                                const float* __restrict__ gam,
                                const float* __restrict__ bet,
                                float* __restrict__ out, int S) {
    int tok = blockIdx.x;
    int s = tok % S;
    int id = ids[tok];
    float vv[3];
    float sum = 0.f;
    #pragma unroll
    for (int kk = 0; kk < 3; kk++) {
        int h = threadIdx.x + kk * 256;
        vv[kk] = wemb[(size_t)id * HID + h] + pemb[(size_t)(s + 2) * HID + h] + tt[h];
        sum += vv[kk];
    }
    sum = block_sum_256(sum);
    float mu = sum * (1.f / HID);
    float q = 0.f;
    #pragma unroll
    for (int kk = 0; kk < 3; kk++) { float d = vv[kk] - mu; q += d * d; }
    q = block_sum_256(q);
    float r = rsqrtf(q * (1.f / HID) + 1e-5f);
    #pragma unroll
    for (int kk = 0; kk < 3; kk++) {
        int h = threadIdx.x + kk * 256;
        out[(size_t)tok * HID + h] = (vv[kk] - mu) * r * gam[h] + bet[h];
    }
}

// ---------------- residual add + layernorm --------------------------------
__global__ void add_ln_kernel(const float* __restrict__ xin,
                              const float* __restrict__ dres,
                              const float* __restrict__ gam,
                              const float* __restrict__ bet,
                              float* __restrict__ xout) {
    size_t base = (size_t)blockIdx.x * HID;
    float vv[3];
    float sum = 0.f;
    #pragma unroll
    for (int kk = 0; kk < 3; kk++) {
        int h = threadIdx.x + kk * 256;
        vv[kk] = xin[base + h] + dres[base + h];
        sum += vv[kk];
    }
    sum = block_sum_256(sum);
    float mu = sum * (1.f / HID);
    float q = 0.f;
    #pragma unroll
    for (int kk = 0; kk < 3; kk++) { float d = vv[kk] - mu; q += d * d; }
    q = block_sum_256(q);
    float r = rsqrtf(q * (1.f / HID) + 1e-5f);
    #pragma unroll
    for (int kk = 0; kk < 3; kk++) {
        int h = threadIdx.x + kk * 256;
        xout[base + h] = (vv[kk] - mu) * r * gam[h] + bet[h];
    }
}

// ---------------- tf32 tensor-core GEMM -----------------------------------
// C[M,N] = A[M,K] @ B[K,N] + bias.  EPI: 0 none, 1 exact gelu, 2 relu.
// 128x128 block tile, BK=16, cp.async double-buffered, 8 warps each 64x32.
// blockIdx.z selects (B, bias, C) triple -> fused QKV.
// Requires N % 128 == 0 and K % 16 == 0 (true for all call sites).

__device__ __forceinline__ void gemm_load_stage(
    float (*As)[20], float (*Bs)[136],
    const float* __restrict__ A, const float* __restrict__ B,
    int row0, int col0, int k0, int M, int N, int K, int tid)
{
    #pragma unroll
    for (int it = 0; it < 2; it++) {
        int id = tid + it * 256;
        int r = id >> 2, qd = id & 3;
        int ar = row0 + r;
        int arc = (ar < M) ? ar : (M - 1);
        cp16(smem_u32(&As[r][qd * 4]), A + (size_t)arc * K + k0 + qd * 4, ar < M);
        int br = id >> 5, bc = id & 31;
        cp16(smem_u32(&Bs[br][bc * 4]), B + (size_t)(k0 + br) * N + col0 + bc * 4, true);
    }
    asm volatile("cp.async.commit_group;\n" ::: "memory");
}

template <int EPI>
__global__ __launch_bounds__(256, 2)
void mma_gemm(const float* __restrict__ A,
              const float* __restrict__ Bq, const float* __restrict__ Bk2,
              const float* __restrict__ Bv,
              const float* __restrict__ biq, const float* __restrict__ bik,
              const float* __restrict__ biv,
              float* __restrict__ Cq, float* __restrict__ Ck,
              float* __restrict__ Cv,
              int M, int N, int K) {
    const float* B    = (blockIdx.z == 0) ? Bq  : (blockIdx.z == 1) ? Bk2 : Bv;
    const float* bias = (blockIdx.z == 0) ? biq : (blockIdx.z == 1) ? bik : biv;
    float*       C    = (blockIdx.z == 0) ? Cq  : (blockIdx.z == 1) ? Ck  : Cv;

    __shared__ float As[2][128][20];
    __shared__ float Bs[2][16][136];

    int tid = threadIdx.x;
    int lane = tid & 31, warp = tid >> 5;
    int wm = warp & 1, wn = warp >> 1;
    int r8 = lane >> 2, c4 = lane & 3;
    int row0 = blockIdx.y * 128, col0 = blockIdx.x * 128;

    float acc[4][4][4];
    #pragma unroll
    for (int m = 0; m < 4; m++)
        #pragma unroll
        for (int n = 0; n < 4; n++)
            #pragma unroll
            for (int i = 0; i < 4; i++) acc[m][n][i] = 0.f;

    gemm_load_stage(As[0], Bs[0], A, B, row0, col0, 0, M, N, K, tid);

    int cur = 0;
    for (int k0 = 0; k0 < K; k0 += 16) {
        if (k0 + 16 < K) {
            gemm_load_stage(As[cur ^ 1], Bs[cur ^ 1], A, B, row0, col0, k0 + 16, M, N, K, tid);
            asm volatile("cp.async.wait_group 1;\n" ::: "memory");
        } else {
            asm volatile("cp.async.wait_group 0;\n" ::: "memory");
        }
        __syncthreads();

        #pragma unroll
        for (int kk = 0; kk < 16; kk += 8) {
            unsigned af[4][4], bf[4][2];
            #pragma unroll
            for (int m = 0; m < 4; m++) {
                int ar = wm * 64 + m * 16 + r8;
                af[m][0] = f2tf(As[cur][ar][kk + c4]);
                af[m][1] = f2tf(As[cur][ar + 8][kk + c4]);
                af[m][2] = f2tf(As[cur][ar][kk + c4 + 4]);
                af[m][3] = f2tf(As[cur][ar + 8][kk + c4 + 4]);
            }
            #pragma unroll
            for (int n = 0; n < 4; n++) {
                int bc = wn * 32 + n * 8 + r8;
                bf[n][0] = f2tf(Bs[cur][kk + c4][bc]);
                bf[n][1] = f2tf(Bs[cur][kk + c4 + 4][bc]);
            }
            #pragma unroll
            for (int m = 0; m < 4; m++)
                #pragma unroll
                for (int n = 0; n < 4; n++)
                    mma8(acc[m][n], af[m], bf[n]);
        }
        __syncthreads();
        cur ^= 1;
    }

    // epilogue
    #pragma unroll
    for (int m = 0; m < 4; m++) {
        int r = row0 + wm * 64 + m * 16 + r8;
        #pragma unroll
        for (int n = 0; n < 4; n++) {
            int c = col0 + wn * 32 + n * 8 + c4 * 2;
            float b0 = bias[c], b1 = bias[c + 1];
            #pragma unroll
            for (int half = 0; half < 2; half++) {
                int rr = r + half * 8;
                if (rr >= M) continue;
                float v0 = acc[m][n][half * 2 + 0] + b0;
                float v1 = acc[m][n][half * 2 + 1] + b1;
                if (EPI == 1) {
                    v0 = 0.5f * v0 * (1.f + erff(v0 * 0.70710678118654752440f));
                    v1 = 0.5f * v1 * (1.f + erff(v1 * 0.70710678118654752440f));
                }
                if (EPI == 2) { v0 = fmaxf(v0, 0.f); v1 = fmaxf(v1, 0.f); }
                C[(size_t)rr * N + c]     = v0;
                C[(size_t)rr * N + c + 1] = v1;
            }
        }
    }
}

// ---------------- sliding-window attention --------------------------------
// grid: (nc*4, NH, B); block 128 threads. 64 queries per block, online
// softmax over the band-restricted key window (18 tiles of 32 keys).
__global__ __launch_bounds__(128)
void slide_attn_kernel(const float* __restrict__ q, const float* __restrict__ k,
                       const float* __restrict__ v, const int* __restrict__ amask,
                       float* __restrict__ out, int S) {
    __shared__ float Qs[64][68];
    __shared__ float Ks[32][68];
    __shared__ float Vs[32][68];
    __shared__ int kval[32];

    int n = blockIdx.x >> 2, qt = blockIdx.x & 3;
    int h = blockIdx.y, b = blockIdx.z;
    int tid = threadIdx.x;
    int q0 = n * CWIN + qt * 64;

    #pragma unroll
    for (int it = 0; it < 8; it++) {
        int lin = tid + it * 128;
        int r = lin >> 4, d4 = (lin & 15) * 4;
        float4 qv = *(const float4*)&q[((size_t)(b * S + q0 + r)) * HID + h * HD + d4];
        qv.x *= 0.125f; qv.y *= 0.125f; qv.z *= 0.125f; qv.w *= 0.125f;
        *(float4*)&Qs[r][d4] = qv;
    }

    int row = tid >> 1, half = tid & 1;
    int iq = qt * 64 + row;
    int kbase = n * CWIN - CWIN;
    float m = -1e30f, l = 0.f;
    float acc[64];
    #pragma unroll
    for (int d = 0; d < 64; d++) acc[d] = 0.f;

    // band restriction: valid window positions for this query tile are
    // [qt*64, qt*64 + 576)  -> 18 key tiles of 32
    int j_lo = qt * 64;
    int j_hi = qt * 64 + 576;

    for (int j0 = j_lo; j0 < j_hi; j0 += 32) {
        __syncthreads();
        #pragma unroll
        for (int it = 0; it < 4; it++) {
            int lin = tid + it * 128;
            int jj = lin >> 4, d4 = (lin & 15) * 4;
            int g = kbase + j0 + jj;
            bool ok = (g >= 0) && (g < S) && (amask[b * S + g] != 0);
            float4 kv = make_float4(0.f, 0.f, 0.f, 0.f);
            float4 vv = make_float4(0.f, 0.f, 0.f, 0.f);
            if (ok) {
                size_t off = ((size_t)(b * S + g)) * HID + h * HD + d4;
                kv = *(const float4*)&k[off];
                vv = *(const float4*)&v[off];
            }
            *(float4*)&Ks[jj][d4] = kv;
            *(float4*)&Vs[jj][d4] = vv;
            if (d4 == 0) kval[jj] = ok ? 1 : 0;
        }
        __syncthreads();

        float s[16];
        #pragma unroll
        for (int u = 0; u < 16; u++) s[u] = 0.f;
        #pragma unroll
        for (int d4 = 0; d4 < 64; d4 += 4) {
            float4 qv = *(const float4*)&Qs[row][d4];
            #pragma unroll
            for (int u = 0; u < 16; u++) {
                float4 kv = *(const float4*)&Ks[half * 16 + u][d4];
                s[u] += qv.x * kv.x + qv.y * kv.y + qv.z * kv.z + qv.w * kv.w;
            }
        }
        float tmax = -1e30f;
        #pragma unroll
        for (int u = 0; u < 16; u++) {
            int t = j0 + half * 16 + u;
            bool valid = (t >= iq) && (t <= iq + 2 * CWIN) && (kval[half * 16 + u] != 0);
            s[u] = valid ? s[u] : -1e9f;
            tmax = fmaxf(tmax, s[u]);
        }
        tmax = fmaxf(tmax, __shfl_xor_sync(0xffffffffu, tmax, 1));
        float mnew = fmaxf(m, tmax);
        float corr = __expf(m - mnew);
        l *= corr;
        #pragma unroll
        for (int d = 0; d < 64; d++) acc[d] *= corr;
        #pragma unroll
        for (int u = 0; u < 16; u++) {
            float p = __expf(s[u] - mnew);
            l += p;
            #pragma unroll
            for (int d4 = 0; d4 < 64; d4 += 4) {
                float4 vv = *(const float4*)&Vs[half * 16 + u][d4];
                acc[d4 + 0] += p * vv.x; acc[d4 + 1] += p * vv.y;
                acc[d4 + 2] += p * vv.z; acc[d4 + 3] += p * vv.w;
            }
        }
        m = mnew;
    }

    l += __shfl_xor_sync(0xffffffffu, l, 1);
    #pragma unroll
    for (int d = 0; d < 64; d++) acc[d] += __shfl_xor_sync(0xffffffffu, acc[d], 1);
    float inv = 1.f / l;
    size_t obase = ((size_t)(b * S + q0 + row)) * HID + h * HD + half * 32;
    #pragma unroll
    for (int d = 0; d < 32; d++) out[obase + d] = acc[half * 32 + d] * inv;
}

// ---------------- span pooling ------------------------------------------
__global__ void span_pool_kernel(const float* __restrict__ masks,
                                 const float* __restrict__ seq,
                                 const int* __restrict__ sidx,
                                 float* __restrict__ emb, int S) {
    int t = blockIdx.x;
    int b = sidx[t];
    __shared__ float mch[256];
    float lenp = 0.f;
    for (int s = threadIdx.x; s < S; s += 256) lenp += masks[t * S + s];
    float len = block_sum_256(lenp);
    len = fmaxf(len, 1e-9f);
    float e[3] = {0.f, 0.f, 0.f};
    for (int s0 = 0; s0 < S; s0 += 256) {
        __syncthreads();
        mch[threadIdx.x] = masks[t * S + s0 + threadIdx.x];
        __syncthreads();
        for (int ss = 0; ss < 256; ss++) {
            float mv = mch[ss];
            size_t base = ((size_t)(b * S + s0 + ss)) * HID;
            #pragma unroll
            for (int kk = 0; kk < 3; kk++)
                e[kk] += mv * seq[base + threadIdx.x + kk * 256];
        }
    }
    float inv = 1.f / len;
    #pragma unroll
    for (int kk = 0; kk < 3; kk++)
        emb[t * HID + threadIdx.x + kk * 256] = e[kk] * inv;
}

// ---------------- row-wise L2 normalize ----------------------------------
__global__ void l2norm_kernel(const float* __restrict__ p, float* __restrict__ out) {
    int t = blockIdx.x;
    float v = p[t * PDIM + threadIdx.x];
    float sq = v * v;
    __shared__ float sh[4];
    #pragma unroll
    for (int o = 16; o > 0; o >>= 1) sq += __shfl_xor_sync(0xffffffffu, sq, o);
    int w = threadIdx.x >> 5;
    if ((threadIdx.x & 31) == 0) sh[w] = sq;
    __syncthreads();
    float nrm = sqrtf(sh[0] + sh[1] + sh[2] + sh[3]);
    out[t * PDIM + threadIdx.x] = v / fmaxf(nrm, 1e-12f);
}

// ---------------- host orchestration ------------------------------------
struct Weights {
    const float *wemb, *pemb, *tt, *lng, *lnb;
    const float *Wq, *bq, *Wk, *bk, *Wv, *bv, *Wo, *bo;
    const float *ln1g, *ln1b, *W1, *b1, *W2, *b2, *ln2g, *ln2b;
};

static void run_encoder(const int* ids, const int* am, int B, int S, float* x,
                        float* qb, float* kb, float* vb, float* ab, float* tb,
                        float* hb, const Weights& W) {
    int M = B * S;
    embed_ln_kernel<<<M, 256>>>(ids, W.wemb, W.pemb, W.tt, W.lng, W.lnb, x, S);
    int nc = S / CWIN;
    dim3 gqkv(HID / 128, M / 128, 3);
    dim3 g768(HID / 128, M / 128, 1);
    dim3 gff(FF / 128, M / 128, 1);
    for (int l = 0; l < NLAYER; l++) {
        const float* wq = W.Wq + (size_t)l * HID * HID;
        const float* wk = W.Wk + (size_t)l * HID * HID;
        const float* wv = W.Wv + (size_t)l * HID * HID;
        const float* wo = W.Wo + (size_t)l * HID * HID;
        const float* w1 = W.W1 + (size_t)l * HID * FF;
        const float* w2 = W.W2 + (size_t)l * FF * HID;
        const float* bq = W.bq + l * HID;
        const float* bk = W.bk + l * HID;
        const float* bv = W.bv + l * HID;
        const float* bo = W.bo + l * HID;
        // fused QKV
        mma_gemm<0><<<gqkv, 256>>>(x, wq, wk, wv, bq, bk, bv, qb, kb, vb, M, HID, HID);
        slide_attn_kernel<<<dim3(nc * 4, NH, B), 128>>>(qb, kb, vb, am, ab, S);
        mma_gemm<0><<<g768, 256>>>(ab, wo, wo, wo, bo, bo, bo, tb, tb, tb, M, HID, HID);
        add_ln_kernel<<<M, 256>>>(x, tb, W.ln1g + l * HID, W.ln1b + l * HID, x);
        mma_gemm<1><<<gff, 256>>>(x, w1, w1, w1, W.b1 + l * FF, W.b1 + l * FF, W.b1 + l * FF,
                                  hb, hb, hb, M, FF, HID);
        mma_gemm<0><<<g768, 256>>>(hb, w2, w2, w2, W.b2 + l * HID, W.b2 + l * HID, W.b2 + l * HID,
                                   tb, tb, tb, M, HID, FF);
        add_ln_kernel<<<M, 256>>>(x, tb, W.ln2g + l * HID, W.ln2b + l * HID, x);
    }
}

extern "C" void kernel_launch(void* const* d_in, const int* in_sizes, int n_in,
                              void* d_out, int out_size) {
    const int*   doc_ids   = (const int*)d_in[0];
    const int*   doc_am    = (const int*)d_in[1];
    const int*   sum_ids   = (const int*)d_in[2];
    const int*   sum_am    = (const int*)d_in[3];
    const float* og_masks  = (const float*)d_in[4];
    const float* llm_masks = (const float*)d_in[5];
    const int*   sidx      = (const int*)d_in[6];

    Weights W;
    W.wemb = (const float*)d_in[7];
    W.pemb = (const float*)d_in[8];
    W.tt   = (const float*)d_in[9];
    W.lng  = (const float*)d_in[10];
    W.lnb  = (const float*)d_in[11];
    W.Wq = (const float*)d_in[12]; W.bq = (const float*)d_in[13];
    W.Wk = (const float*)d_in[14]; W.bk = (const float*)d_in[15];
    W.Wv = (const float*)d_in[16]; W.bv = (const float*)d_in[17];
    W.Wo = (const float*)d_in[18]; W.bo = (const float*)d_in[19];
    W.ln1g = (const float*)d_in[20]; W.ln1b = (const float*)d_in[21];
    W.W1 = (const float*)d_in[22]; W.b1 = (const float*)d_in[23];
    W.W2 = (const float*)d_in[24]; W.b2 = (const float*)d_in[25];
    W.ln2g = (const float*)d_in[26]; W.ln2b = (const float*)d_in[27];
    const float* pW1 = (const float*)d_in[28];
    const float* pb1 = (const float*)d_in[29];
    const float* pW2 = (const float*)d_in[30];
    const float* pb2 = (const float*)d_in[31];
    float* out = (float*)d_out;

    float *xdoc, *xsum, *qb, *kb, *vb, *ab, *tb, *hb, *emb, *p1, *p2;
    cudaGetSymbolAddress((void**)&xdoc, g_xdoc);
    cudaGetSymbolAddress((void**)&xsum, g_xsum);
    cudaGetSymbolAddress((void**)&qb, g_q);
    cudaGetSymbolAddress((void**)&kb, g_k);
    cudaGetSymbolAddress((void**)&vb, g_v);
    cudaGetSymbolAddress((void**)&ab, g_a);
    cudaGetSymbolAddress((void**)&tb, g_t);
    cudaGetSymbolAddress((void**)&hb, g_h);
    cudaGetSymbolAddress((void**)&emb, g_emb);
    cudaGetSymbolAddress((void**)&p1, g_p1);
    cudaGetSymbolAddress((void**)&p2, g_p2);

    run_encoder(doc_ids, doc_am, B_DOC, S_DOC, xdoc, qb, kb, vb, ab, tb, hb, W);
    run_encoder(sum_ids, sum_am, B_DOC, S_SUM, xsum, qb, kb, vb, ab, tb, hb, W);

    // human spans (doc)
    span_pool_kernel<<<16, 256>>>(og_masks, xdoc, sidx, emb, S_DOC);
    mma_gemm<2><<<dim3(HID / 128, 1, 1), 256>>>(emb, pW1, pW1, pW1, pb1, pb1, pb1,
                                                p1, p1, p1, 16, HID, HID);
    mma_gemm<0><<<dim3(PDIM / 128, 1, 1), 256>>>(p1, pW2, pW2, pW2, pb2, pb2, pb2,
                                                 p2, p2, p2, 16, PDIM, HID);
    l2norm_kernel<<<16, PDIM>>>(p2, out);

    // llm spans (summary)
    span_pool_kernel<<<16, 256>>>(llm_masks, xsum, sidx, emb, S_SUM);
    mma_gemm<2><<<dim3(HID / 128, 1, 1), 256>>>(emb, pW1, pW1, pW1, pb1, pb1, pb1,
                                                p1, p1, p1, 16, HID, HID);
    mma_gemm<0><<<dim3(PDIM / 128, 1, 1), 256>>>(p1, pW2, pW2, pW2, pb2, pb2, pb2,
                                                 p2, p2, p2, 16, PDIM, HID);
    l2norm_kernel<<<16, PDIM>>>(p2, out + 16 * PDIM);
}

// round 10
// speedup vs baseline: 3.3798x; 1.3675x over previous
#include <cuda_runtime.h>
#include <cuda_bf16.h>
#include <math.h>

// ---------------- problem constants ----------------
#define HID 768
#define NH 12
#define HD 64
#define FF 3072
#define NLAYER 12
#define CWIN 256
#define PDIM 128

#define B_DOC 2
#define S_DOC 2048
#define S_SUM 512
#define M_DOC (B_DOC * S_DOC)   // 4096
#define M_SUM (B_DOC * S_SUM)   // 1024

// ---------------- scratch (device globals; no allocation allowed) -------
__device__ __align__(256) float g_xdoc[M_DOC * HID];
__device__ __align__(256) float g_xsum[M_SUM * HID];
__device__ __align__(256) float g_q[M_DOC * HID];
__device__ __align__(256) float g_k[M_DOC * HID];
__device__ __align__(256) float g_v[M_DOC * HID];
__device__ __align__(256) float g_a[M_DOC * HID];
__device__ __align__(256) float g_t[M_DOC * HID];
__device__ __align__(256) float g_h[M_DOC * FF];
__device__ __align__(256) float g_emb[16 * HID];
__device__ __align__(256) float g_p1[16 * HID];
__device__ __align__(256) float g_p2[16 * PDIM];

// ---------------- helpers ----------------
__device__ __forceinline__ float block_sum_256(float v) {
    __shared__ float sh[8];
    #pragma unroll
    for (int o = 16; o > 0; o >>= 1) v += __shfl_xor_sync(0xffffffffu, v, o);
    int w = threadIdx.x >> 5;
    if ((threadIdx.x & 31) == 0) sh[w] = v;
    __syncthreads();
    if (threadIdx.x < 8) {
        float r = sh[threadIdx.x];
        #pragma unroll
        for (int o = 4; o > 0; o >>= 1) r += __shfl_xor_sync(0x000000ffu, r, o);
        if (threadIdx.x == 0) sh[0] = r;
    }
    __syncthreads();
    float out = sh[0];
    __syncthreads();
    return out;
}

__device__ __forceinline__ unsigned smem_u32(const void* p) {
    return (unsigned)__cvta_generic_to_shared(p);
}

__device__ __forceinline__ void cp16(unsigned s, const void* g, bool pred) {
    asm volatile("cp.async.cg.shared.global [%0], [%1], 16, %2;\n"
                 :: "r"(s), "l"(g), "r"(pred ? 16 : 0));
}

__device__ __forceinline__ unsigned f2tf(float x) {
    unsigned r;
    asm("cvt.rna.tf32.f32 %0, %1;" : "=r"(r) : "f"(x));
    return r;
}

// split x = big + small (both exactly representable in tf32)
__device__ __forceinline__ void tfsplit(float x, unsigned& b, unsigned& s) {
    b = f2tf(x);
    s = f2tf(x - __uint_as_float(b));
}

__device__ __forceinline__ void mma8(float* c, const unsigned* a, const unsigned* b) {
    asm volatile(
        "mma.sync.aligned.m16n8k8.row.col.f32.tf32.tf32.f32 "
        "{%0,%1,%2,%3}, {%4,%5,%6,%7}, {%8,%9}, {%0,%1,%2,%3};"
        : "+f"(c[0]), "+f"(c[1]), "+f"(c[2]), "+f"(c[3])
        : "r"(a[0]), "r"(a[1]), "r"(a[2]), "r"(a[3]), "r"(b[0]), "r"(b[1]));
}

// ---------------- embedding + layernorm ----------------------------------
__global__ void embed_ln_kernel(const int* __restrict__ ids,
                                const float* __restrict__ wemb,
                                const float* __restrict__ pemb,
                                const float* __restrict__ tt,
                                const float* __restrict__ gam,
                                const float* __restrict__ bet,
                                float* __restrict__ out, int S) {
    int tok = blockIdx.x;
    int s = tok % S;
    int id = ids[tok];
    float vv[3];
    float sum = 0.f;
    #pragma unroll
    for (int kk = 0; kk < 3; kk++) {
        int h = threadIdx.x + kk * 256;
        vv[kk] = wemb[(size_t)id * HID + h] + pemb[(size_t)(s + 2) * HID + h] + tt[h];
        sum += vv[kk];
    }
    sum = block_sum_256(sum);
    float mu = sum * (1.f / HID);
    float q = 0.f;
    #pragma unroll
    for (int kk = 0; kk < 3; kk++) { float d = vv[kk] - mu; q += d * d; }
    q = block_sum_256(q);
    float r = rsqrtf(q * (1.f / HID) + 1e-5f);
    #pragma unroll
    for (int kk = 0; kk < 3; kk++) {
        int h = threadIdx.x + kk * 256;
        out[(size_t)tok * HID + h] = (vv[kk] - mu) * r * gam[h] + bet[h];
    }
}

// ---------------- residual add + layernorm --------------------------------
__global__ void add_ln_kernel(const float* __restrict__ xin,
                              const float* __restrict__ dres,
                              const float* __restrict__ gam,
                              const float* __restrict__ bet,
                              float* __restrict__ xout) {
    size_t base = (size_t)blockIdx.x * HID;
    float vv[3];
    float sum = 0.f;
    #pragma unroll
    for (int kk = 0; kk < 3; kk++) {
        int h = threadIdx.x + kk * 256;
        vv[kk] = xin[base + h] + dres[base + h];
        sum += vv[kk];
    }
    sum = block_sum_256(sum);
    float mu = sum * (1.f / HID);
    float q = 0.f;
    #pragma unroll
    for (int kk = 0; kk < 3; kk++) { float d = vv[kk] - mu; q += d * d; }
    q = block_sum_256(q);
    float r = rsqrtf(q * (1.f / HID) + 1e-5f);
    #pragma unroll
    for (int kk = 0; kk < 3; kk++) {
        int h = threadIdx.x + kk * 256;
        xout[base + h] = (vv[kk] - mu) * r * gam[h] + bet[h];
    }
}

// ---------------- tf32 tensor-core GEMM -----------------------------------
__device__ __forceinline__ void gemm_load_stage(
    float (*As)[20], float (*Bs)[136],
    const float* __restrict__ A, const float* __restrict__ B,
    int row0, int col0, int k0, int M, int N, int K, int tid)
{
    #pragma unroll
    for (int it = 0; it < 2; it++) {
        int id = tid + it * 256;
        int r = id >> 2, qd = id & 3;
        int ar = row0 + r;
        int arc = (ar < M) ? ar : (M - 1);
        cp16(smem_u32(&As[r][qd * 4]), A + (size_t)arc * K + k0 + qd * 4, ar < M);
        int br = id >> 5, bc = id & 31;
        cp16(smem_u32(&Bs[br][bc * 4]), B + (size_t)(k0 + br) * N + col0 + bc * 4, true);
    }
    asm volatile("cp.async.commit_group;\n" ::: "memory");
}

template <int EPI>
__global__ __launch_bounds__(256, 2)
void mma_gemm(const float* __restrict__ A,
              const float* __restrict__ Bq, const float* __restrict__ Bk2,
              const float* __restrict__ Bv,
              const float* __restrict__ biq, const float* __restrict__ bik,
              const float* __restrict__ biv,
              float* __restrict__ Cq, float* __restrict__ Ck,
              float* __restrict__ Cv,
              int M, int N, int K) {
    const float* B    = (blockIdx.z == 0) ? Bq  : (blockIdx.z == 1) ? Bk2 : Bv;
    const float* bias = (blockIdx.z == 0) ? biq : (blockIdx.z == 1) ? bik : biv;
    float*       C    = (blockIdx.z == 0) ? Cq  : (blockIdx.z == 1) ? Ck  : Cv;

    __shared__ float As[2][128][20];
    __shared__ float Bs[2][16][136];

    int tid = threadIdx.x;
    int lane = tid & 31, warp = tid >> 5;
    int wm = warp & 1, wn = warp >> 1;
    int r8 = lane >> 2, c4 = lane & 3;
    int row0 = blockIdx.y * 128, col0 = blockIdx.x * 128;

    float acc[4][4][4];
    #pragma unroll
    for (int m = 0; m < 4; m++)
        #pragma unroll
        for (int n = 0; n < 4; n++)
            #pragma unroll
            for (int i = 0; i < 4; i++) acc[m][n][i] = 0.f;

    gemm_load_stage(As[0], Bs[0], A, B, row0, col0, 0, M, N, K, tid);

    int cur = 0;
    for (int k0 = 0; k0 < K; k0 += 16) {
        if (k0 + 16 < K) {
            gemm_load_stage(As[cur ^ 1], Bs[cur ^ 1], A, B, row0, col0, k0 + 16, M, N, K, tid);
            asm volatile("cp.async.wait_group 1;\n" ::: "memory");
        } else {
            asm volatile("cp.async.wait_group 0;\n" ::: "memory");
        }
        __syncthreads();

        #pragma unroll
        for (int kk = 0; kk < 16; kk += 8) {
            unsigned af[4][4], bf[4][2];
            #pragma unroll
            for (int m = 0; m < 4; m++) {
                int ar = wm * 64 + m * 16 + r8;
                af[m][0] = f2tf(As[cur][ar][kk + c4]);
                af[m][1] = f2tf(As[cur][ar + 8][kk + c4]);
                af[m][2] = f2tf(As[cur][ar][kk + c4 + 4]);
                af[m][3] = f2tf(As[cur][ar + 8][kk + c4 + 4]);
            }
            #pragma unroll
            for (int n = 0; n < 4; n++) {
                int bc = wn * 32 + n * 8 + r8;
                bf[n][0] = f2tf(Bs[cur][kk + c4][bc]);
                bf[n][1] = f2tf(Bs[cur][kk + c4 + 4][bc]);
            }
            #pragma unroll
            for (int m = 0; m < 4; m++)
                #pragma unroll
                for (int n = 0; n < 4; n++)
                    mma8(acc[m][n], af[m], bf[n]);
        }
        __syncthreads();
        cur ^= 1;
    }

    #pragma unroll
    for (int m = 0; m < 4; m++) {
        int r = row0 + wm * 64 + m * 16 + r8;
        #pragma unroll
        for (int n = 0; n < 4; n++) {
            int c = col0 + wn * 32 + n * 8 + c4 * 2;
            float b0 = bias[c], b1 = bias[c + 1];
            #pragma unroll
            for (int half = 0; half < 2; half++) {
                int rr = r + half * 8;
                if (rr >= M) continue;
                float v0 = acc[m][n][half * 2 + 0] + b0;
                float v1 = acc[m][n][half * 2 + 1] + b1;
                if (EPI == 1) {
                    v0 = 0.5f * v0 * (1.f + erff(v0 * 0.70710678118654752440f));
                    v1 = 0.5f * v1 * (1.f + erff(v1 * 0.70710678118654752440f));
                }
                if (EPI == 2) { v0 = fmaxf(v0, 0.f); v1 = fmaxf(v1, 0.f); }
                C[(size_t)rr * N + c]     = v0;
                C[(size_t)rr * N + c + 1] = v1;
            }
        }
    }
}

// ---------------- tensor-core sliding-window attention --------------------
// grid: (nc*4, NH, B); block 128 threads (4 warps). Each block: 64 queries.
// Warp w owns query rows [w*16, w*16+16). Key loop over the band-restricted
// 576-key window in 32-key tiles. QK^T and PV via m16n8k8 tf32 with
// error-compensated 3-mma split (fp32-level accuracy).
__global__ __launch_bounds__(128)
void slide_attn_mma(const float* __restrict__ q, const float* __restrict__ k,
                    const float* __restrict__ v, const int* __restrict__ amask,
                    float* __restrict__ out, int S) {
    __shared__ float Qs[64][68];
    __shared__ float Ks[32][68];
    __shared__ float Vs[32][68];
    __shared__ float Ps[4][16][36];
    __shared__ int kval[32];

    int n = blockIdx.x >> 2, qt = blockIdx.x & 3;
    int h = blockIdx.y, b = blockIdx.z;
    int tid = threadIdx.x;
    int lane = tid & 31, warp = tid >> 5;
    int r8 = lane >> 2, c4 = lane & 3;
    int q0 = n * CWIN + qt * 64;

    // stage Q tile (pre-scaled by 1/sqrt(64))
    #pragma unroll
    for (int it = 0; it < 8; it++) {
        int lin = tid + it * 128;
        int r = lin >> 4, d4 = (lin & 15) * 4;
        float4 qv = *(const float4*)&q[((size_t)(b * S + q0 + r)) * HID + h * HD + d4];
        qv.x *= 0.125f; qv.y *= 0.125f; qv.z *= 0.125f; qv.w *= 0.125f;
        *(float4*)&Qs[r][d4] = qv;
    }

    int iq_lo = qt * 64 + warp * 16 + r8;   // within-chunk query index (lo rows)
    int iq_hi = iq_lo + 8;
    int kbase = n * CWIN - CWIN;

    float m_lo = -1e30f, m_hi = -1e30f, l_lo = 0.f, l_hi = 0.f;
    float o[8][4];
    #pragma unroll
    for (int nt = 0; nt < 8; nt++)
        #pragma unroll
        for (int i = 0; i < 4; i++) o[nt][i] = 0.f;

    int j_lo = qt * 64, j_hi = qt * 64 + 576;
    for (int j0 = j_lo; j0 < j_hi; j0 += 32) {
        __syncthreads();
        // stage K,V tile (32 keys) with validity
        #pragma unroll
        for (int it = 0; it < 4; it++) {
            int lin = tid + it * 128;
            int jj = lin >> 4, d4 = (lin & 15) * 4;
            int g = kbase + j0 + jj;
            bool ok = (g >= 0) && (g < S) && (amask[b * S + g] != 0);
            float4 kv = make_float4(0.f, 0.f, 0.f, 0.f);
            float4 vv = make_float4(0.f, 0.f, 0.f, 0.f);
            if (ok) {
                size_t off = ((size_t)(b * S + g)) * HID + h * HD + d4;
                kv = *(const float4*)&k[off];
                vv = *(const float4*)&v[off];
            }
            *(float4*)&Ks[jj][d4] = kv;
            *(float4*)&Vs[jj][d4] = vv;
            if (d4 == 0) kval[jj] = ok ? 1 : 0;
        }
        __syncthreads();

        // ---- S = Q @ K^T  (16x32 per warp), 3-mma split -----------------
        float sacc[4][4];
        #pragma unroll
        for (int j = 0; j < 4; j++)
            #pragma unroll
            for (int i = 0; i < 4; i++) sacc[j][i] = 0.f;

        #pragma unroll
        for (int kk = 0; kk < 64; kk += 8) {
            unsigned ab[4], as[4];
            tfsplit(Qs[warp * 16 + r8][kk + c4],          ab[0], as[0]);
            tfsplit(Qs[warp * 16 + r8 + 8][kk + c4],      ab[1], as[1]);
            tfsplit(Qs[warp * 16 + r8][kk + c4 + 4],      ab[2], as[2]);
            tfsplit(Qs[warp * 16 + r8 + 8][kk + c4 + 4],  ab[3], as[3]);
            #pragma unroll
            for (int j = 0; j < 4; j++) {
                unsigned bb[2], bs[2];
                tfsplit(Ks[j * 8 + r8][kk + c4],     bb[0], bs[0]);
                tfsplit(Ks[j * 8 + r8][kk + c4 + 4], bb[1], bs[1]);
                mma8(sacc[j], ab, bb);
                mma8(sacc[j], ab, bs);
                mma8(sacc[j], as, bb);
            }
        }

        // ---- mask ---------------------------------------------------------
        #pragma unroll
        for (int j = 0; j < 4; j++) {
            int t0 = j0 + j * 8 + 2 * c4;
            int t1 = t0 + 1;
            bool k0 = kval[j * 8 + 2 * c4] != 0;
            bool k1 = kval[j * 8 + 2 * c4 + 1] != 0;
            if (!(k0 && t0 >= iq_lo && t0 <= iq_lo + 2 * CWIN)) sacc[j][0] = -1e9f;
            if (!(k1 && t1 >= iq_lo && t1 <= iq_lo + 2 * CWIN)) sacc[j][1] = -1e9f;
            if (!(k0 && t0 >= iq_hi && t0 <= iq_hi + 2 * CWIN)) sacc[j][2] = -1e9f;
            if (!(k1 && t1 >= iq_hi && t1 <= iq_hi + 2 * CWIN)) sacc[j][3] = -1e9f;
        }

        // ---- online softmax ----------------------------------------------
        float mx_lo = -1e30f, mx_hi = -1e30f;
        #pragma unroll
        for (int j = 0; j < 4; j++) {
            mx_lo = fmaxf(mx_lo, fmaxf(sacc[j][0], sacc[j][1]));
            mx_hi = fmaxf(mx_hi, fmaxf(sacc[j][2], sacc[j][3]));
        }
        mx_lo = fmaxf(mx_lo, __shfl_xor_sync(0xffffffffu, mx_lo, 1));
        mx_lo = fmaxf(mx_lo, __shfl_xor_sync(0xffffffffu, mx_lo, 2));
        mx_hi = fmaxf(mx_hi, __shfl_xor_sync(0xffffffffu, mx_hi, 1));
        mx_hi = fmaxf(mx_hi, __shfl_xor_sync(0xffffffffu, mx_hi, 2));

        float mn_lo = fmaxf(m_lo, mx_lo);
        float mn_hi = fmaxf(m_hi, mx_hi);
        float corr_lo = __expf(m_lo - mn_lo);
        float corr_hi = __expf(m_hi - mn_hi);
        m_lo = mn_lo; m_hi = mn_hi;

        float rs_lo = 0.f, rs_hi = 0.f;
        #pragma unroll
        for (int j = 0; j < 4; j++) {
            sacc[j][0] = __expf(sacc[j][0] - mn_lo);
            sacc[j][1] = __expf(sacc[j][1] - mn_lo);
            sacc[j][2] = __expf(sacc[j][2] - mn_hi);
            sacc[j][3] = __expf(sacc[j][3] - mn_hi);
            rs_lo += sacc[j][0] + sacc[j][1];
            rs_hi += sacc[j][2] + sacc[j][3];
        }
        rs_lo += __shfl_xor_sync(0xffffffffu, rs_lo, 1);
        rs_lo += __shfl_xor_sync(0xffffffffu, rs_lo, 2);
        rs_hi += __shfl_xor_sync(0xffffffffu, rs_hi, 1);
        rs_hi += __shfl_xor_sync(0xffffffffu, rs_hi, 2);
        l_lo = l_lo * corr_lo + rs_lo;
        l_hi = l_hi * corr_hi + rs_hi;

        // rescale O accumulators
        #pragma unroll
        for (int nt = 0; nt < 8; nt++) {
            o[nt][0] *= corr_lo; o[nt][1] *= corr_lo;
            o[nt][2] *= corr_hi; o[nt][3] *= corr_hi;
        }

        // ---- write P to warp-private smem --------------------------------
        #pragma unroll
        for (int j = 0; j < 4; j++) {
            *(float2*)&Ps[warp][r8][j * 8 + 2 * c4]     = make_float2(sacc[j][0], sacc[j][1]);
            *(float2*)&Ps[warp][r8 + 8][j * 8 + 2 * c4] = make_float2(sacc[j][2], sacc[j][3]);
        }
        __syncwarp();

        // ---- O += P @ V  (16x64 per warp), 3-mma split -------------------
        #pragma unroll
        for (int kk2 = 0; kk2 < 32; kk2 += 8) {
            unsigned ab[4], as[4];
            tfsplit(Ps[warp][r8][kk2 + c4],         ab[0], as[0]);
            tfsplit(Ps[warp][r8 + 8][kk2 + c4],     ab[1], as[1]);
            tfsplit(Ps[warp][r8][kk2 + c4 + 4],     ab[2], as[2]);
            tfsplit(Ps[warp][r8 + 8][kk2 + c4 + 4], ab[3], as[3]);
            #pragma unroll
            for (int nt = 0; nt < 8; nt++) {
                unsigned bb[2], bs[2];
                tfsplit(Vs[kk2 + c4][nt * 8 + r8],     bb[0], bs[0]);
                tfsplit(Vs[kk2 + c4 + 4][nt * 8 + r8], bb[1], bs[1]);
                mma8(o[nt], ab, bb);
                mma8(o[nt], ab, bs);
                mma8(o[nt], as, bb);
            }
        }
        __syncwarp();
    }

    // ---- epilogue ---------------------------------------------------------
    float inv_lo = 1.f / l_lo, inv_hi = 1.f / l_hi;
    int wrow_lo = q0 + warp * 16 + r8;
    int wrow_hi = wrow_lo + 8;
    #pragma unroll
    for (int nt = 0; nt < 8; nt++) {
        int c = h * HD + nt * 8 + 2 * c4;
        *(float2*)&out[(size_t)(b * S + wrow_lo) * HID + c] =
            make_float2(o[nt][0] * inv_lo, o[nt][1] * inv_lo);
        *(float2*)&out[(size_t)(b * S + wrow_hi) * HID + c] =
            make_float2(o[nt][2] * inv_hi, o[nt][3] * inv_hi);
    }
}

// ---------------- span pooling ------------------------------------------
__global__ void span_pool_kernel(const float* __restrict__ masks,
                                 const float* __restrict__ seq,
                                 const int* __restrict__ sidx,
                                 float* __restrict__ emb, int S) {
    int t = blockIdx.x;
    int b = sidx[t];
    __shared__ float mch[256];
    float lenp = 0.f;
    for (int s = threadIdx.x; s < S; s += 256) lenp += masks[t * S + s];
    float len = block_sum_256(lenp);
    len = fmaxf(len, 1e-9f);
    float e[3] = {0.f, 0.f, 0.f};
    for (int s0 = 0; s0 < S; s0 += 256) {
        __syncthreads();
        mch[threadIdx.x] = masks[t * S + s0 + threadIdx.x];
        __syncthreads();
        for (int ss = 0; ss < 256; ss++) {
            float mv = mch[ss];
            size_t base = ((size_t)(b * S + s0 + ss)) * HID;
            #pragma unroll
            for (int kk = 0; kk < 3; kk++)
                e[kk] += mv * seq[base + threadIdx.x + kk * 256];
        }
    }
    float inv = 1.f / len;
    #pragma unroll
    for (int kk = 0; kk < 3; kk++)
        emb[t * HID + threadIdx.x + kk * 256] = e[kk] * inv;
}

// ---------------- row-wise L2 normalize ----------------------------------
__global__ void l2norm_kernel(const float* __restrict__ p, float* __restrict__ out) {
    int t = blockIdx.x;
    float v = p[t * PDIM + threadIdx.x];
    float sq = v * v;
    __shared__ float sh[4];
    #pragma unroll
    for (int o = 16; o > 0; o >>= 1) sq += __shfl_xor_sync(0xffffffffu, sq, o);
    int w = threadIdx.x >> 5;
    if ((threadIdx.x & 31) == 0) sh[w] = sq;
    __syncthreads();
    float nrm = sqrtf(sh[0] + sh[1] + sh[2] + sh[3]);
    out[t * PDIM + threadIdx.x] = v / fmaxf(nrm, 1e-12f);
}

// ---------------- host orchestration ------------------------------------
struct Weights {
    const float *wemb, *pemb, *tt, *lng, *lnb;
    const float *Wq, *bq, *Wk, *bk, *Wv, *bv, *Wo, *bo;
    const float *ln1g, *ln1b, *W1, *b1, *W2, *b2, *ln2g, *ln2b;
};

static void run_encoder(const int* ids, const int* am, int B, int S, float* x,
                        float* qb, float* kb, float* vb, float* ab, float* tb,
                        float* hb, const Weights& W) {
    int M = B * S;
    embed_ln_kernel<<<M, 256>>>(ids, W.wemb, W.pemb, W.tt, W.lng, W.lnb, x, S);
    int nc = S / CWIN;
    dim3 gqkv(HID / 128, M / 128, 3);
    dim3 g768(HID / 128, M / 128, 1);
    dim3 gff(FF / 128, M / 128, 1);
    for (int l = 0; l < NLAYER; l++) {
        const float* wq = W.Wq + (size_t)l * HID * HID;
        const float* wk = W.Wk + (size_t)l * HID * HID;
        const float* wv = W.Wv + (size_t)l * HID * HID;
        const float* wo = W.Wo + (size_t)l * HID * HID;
        const float* w1 = W.W1 + (size_t)l * HID * FF;
        const float* w2 = W.W2 + (size_t)l * FF * HID;
        const float* bq = W.bq + l * HID;
        const float* bk = W.bk + l * HID;
        const float* bv = W.bv + l * HID;
        const float* bo = W.bo + l * HID;
        mma_gemm<0><<<gqkv, 256>>>(x, wq, wk, wv, bq, bk, bv, qb, kb, vb, M, HID, HID);
        slide_attn_mma<<<dim3(nc * 4, NH, B), 128>>>(qb, kb, vb, am, ab, S);
        mma_gemm<0><<<g768, 256>>>(ab, wo, wo, wo, bo, bo, bo, tb, tb, tb, M, HID, HID);
        add_ln_kernel<<<M, 256>>>(x, tb, W.ln1g + l * HID, W.ln1b + l * HID, x);
        mma_gemm<1><<<gff, 256>>>(x, w1, w1, w1, W.b1 + l * FF, W.b1 + l * FF, W.b1 + l * FF,
                                  hb, hb, hb, M, FF, HID);
        mma_gemm<0><<<g768, 256>>>(hb, w2, w2, w2, W.b2 + l * HID, W.b2 + l * HID, W.b2 + l * HID,
                                   tb, tb, tb, M, HID, FF);
        add_ln_kernel<<<M, 256>>>(x, tb, W.ln2g + l * HID, W.ln2b + l * HID, x);
    }
}

extern "C" void kernel_launch(void* const* d_in, const int* in_sizes, int n_in,
                              void* d_out, int out_size) {
    const int*   doc_ids   = (const int*)d_in[0];
    const int*   doc_am    = (const int*)d_in[1];
    const int*   sum_ids   = (const int*)d_in[2];
    const int*   sum_am    = (const int*)d_in[3];
    const float* og_masks  = (const float*)d_in[4];
    const float* llm_masks = (const float*)d_in[5];
    const int*   sidx      = (const int*)d_in[6];

    Weights W;
    W.wemb = (const float*)d_in[7];
    W.pemb = (const float*)d_in[8];
    W.tt   = (const float*)d_in[9];
    W.lng  = (const float*)d_in[10];
    W.lnb  = (const float*)d_in[11];
    W.Wq = (const float*)d_in[12]; W.bq = (const float*)d_in[13];
    W.Wk = (const float*)d_in[14]; W.bk = (const float*)d_in[15];
    W.Wv = (const float*)d_in[16]; W.bv = (const float*)d_in[17];
    W.Wo = (const float*)d_in[18]; W.bo = (const float*)d_in[19];
    W.ln1g = (const float*)d_in[20]; W.ln1b = (const float*)d_in[21];
    W.W1 = (const float*)d_in[22]; W.b1 = (const float*)d_in[23];
    W.W2 = (const float*)d_in[24]; W.b2 = (const float*)d_in[25];
    W.ln2g = (const float*)d_in[26]; W.ln2b = (const float*)d_in[27];
    const float* pW1 = (const float*)d_in[28];
    const float* pb1 = (const float*)d_in[29];
    const float* pW2 = (const float*)d_in[30];
    const float* pb2 = (const float*)d_in[31];
    float* out = (float*)d_out;

    float *xdoc, *xsum, *qb, *kb, *vb, *ab, *tb, *hb, *emb, *p1, *p2;
    cudaGetSymbolAddress((void**)&xdoc, g_xdoc);
    cudaGetSymbolAddress((void**)&xsum, g_xsum);
    cudaGetSymbolAddress((void**)&qb, g_q);
    cudaGetSymbolAddress((void**)&kb, g_k);
    cudaGetSymbolAddress((void**)&vb, g_v);
    cudaGetSymbolAddress((void**)&ab, g_a);
    cudaGetSymbolAddress((void**)&tb, g_t);
    cudaGetSymbolAddress((void**)&hb, g_h);
    cudaGetSymbolAddress((void**)&emb, g_emb);
    cudaGetSymbolAddress((void**)&p1, g_p1);
    cudaGetSymbolAddress((void**)&p2, g_p2);

    run_encoder(doc_ids, doc_am, B_DOC, S_DOC, xdoc, qb, kb, vb, ab, tb, hb, W);
    run_encoder(sum_ids, sum_am, B_DOC, S_SUM, xsum, qb, kb, vb, ab, tb, hb, W);

    // human spans (doc)
    span_pool_kernel<<<16, 256>>>(og_masks, xdoc, sidx, emb, S_DOC);
    mma_gemm<2><<<dim3(HID / 128, 1, 1), 256>>>(emb, pW1, pW1, pW1, pb1, pb1, pb1,
                                                p1, p1, p1, 16, HID, HID);
    mma_gemm<0><<<dim3(PDIM / 128, 1, 1), 256>>>(p1, pW2, pW2, pW2, pb2, pb2, pb2,
                                                 p2, p2, p2, 16, PDIM, HID);
    l2norm_kernel<<<16, PDIM>>>(p2, out);

    // llm spans (summary)
    span_pool_kernel<<<16, 256>>>(llm_masks, xsum, sidx, emb, S_SUM);
    mma_gemm<2><<<dim3(HID / 128, 1, 1), 256>>>(emb, pW1, pW1, pW1, pb1, pb1, pb1,
                                                p1, p1, p1, 16, HID, HID);
    mma_gemm<0><<<dim3(PDIM / 128, 1, 1), 256>>>(p1, pW2, pW2, pW2, pb2, pb2, pb2,
                                                 p2, p2, p2, 16, PDIM, HID);
    l2norm_kernel<<<16, PDIM>>>(p2, out + 16 * PDIM);
}